// round 2
// baseline (speedup 1.0000x reference)
#include <cuda_runtime.h>
#include <cuda_bf16.h>
#include <cstdint>

// Problem constants
#define Bn 512
#define Tn 512
#define En 64
#define Hn 64
#define Gn 256   // 4*H
#define Cn 8
#define Rr 4     // batch rows per LSTM block

typedef unsigned long long u64;

// Scratch (device globals: no cudaMalloc allowed)
__device__ float g_bufA[Bn * Tn * En];   // 64 MB
__device__ float g_bufB[Bn * Tn * Hn];   // 64 MB
__device__ float g_xw[Bn * Tn * Gn];     // 256 MB

// ---------------------------------------------------------------------------
// packed f32x2 helpers (FFMA2 — only reachable via PTX fma.rn.f32x2)
// ---------------------------------------------------------------------------
__device__ __forceinline__ u64 pack2(float lo, float hi) {
    u64 r; asm("mov.b64 %0, {%1, %2};" : "=l"(r) : "f"(lo), "f"(hi)); return r;
}
__device__ __forceinline__ void unpack2(u64 v, float& lo, float& hi) {
    asm("mov.b64 {%0, %1}, %2;" : "=f"(lo), "=f"(hi) : "l"(v));
}
__device__ __forceinline__ u64 fma2(u64 a, u64 b, u64 c) {
    u64 d; asm("fma.rn.f32x2 %0, %1, %2, %3;" : "=l"(d) : "l"(a), "l"(b), "l"(c));
    return d;
}

__device__ __forceinline__ float sigf(float x) {
    return 1.f / (1.f + __expf(-x));
}
// tanh(x) = 2*sigmoid(2x) - 1, via fast exp (keeps ~1e-6 accuracy)
__device__ __forceinline__ float tanhfast(float x) {
    return 2.f / (1.f + __expf(-2.f * x)) - 1.f;
}

// ---------------------------------------------------------------------------
// Embedding: out[bt][e] = word_table[ids[bt]][e] + pos_table[t][e]
// ---------------------------------------------------------------------------
__global__ void embed_kernel(const int* __restrict__ ids,
                             const float* __restrict__ wt,
                             const float* __restrict__ pt,
                             float* __restrict__ out)
{
    int i = blockIdx.x * blockDim.x + threadIdx.x;   // over B*T*16
    int bt = i >> 4;
    int v  = i & 15;
    int id = ids[bt];
    int t  = bt & (Tn - 1);
    float4 a = ((const float4*)wt)[id * 16 + v];
    float4 p = ((const float4*)pt)[t * 16 + v];
    float4 r;
    r.x = a.x + p.x; r.y = a.y + p.y; r.z = a.z + p.z; r.w = a.w + p.w;
    ((float4*)out)[i] = r;
}

// ---------------------------------------------------------------------------
// XW GEMM: XW[row][j] = sum_k X[row][k] * Wx[k][j] + b[j]
// M = B*T, K = 64, N = 256. Thread = output column j, 64 rows per block.
// Wx column packed into 32 f32x2 regs; X staged in shared, read as f32x2 pairs.
// ---------------------------------------------------------------------------
__global__ void __launch_bounds__(256)
gemm_xw_kernel(const float* __restrict__ X,
               const float* __restrict__ Wx,
               const float* __restrict__ bias,
               float* __restrict__ XW)
{
    const int j = threadIdx.x;
    const int row0 = blockIdx.x * 64;

    __shared__ __align__(16) float xs[64 * 64];   // 64 rows x 64 cols

    // Wx column j -> 32 packed pairs along k
    u64 wp[32];
#pragma unroll
    for (int m = 0; m < 32; m++)
        wp[m] = pack2(Wx[(2 * m) * Gn + j], Wx[(2 * m + 1) * Gn + j]);
    const float bj = bias[j];

    // cooperative load of 64 rows x 64 floats = 1024 float4
    const float4* Xv = (const float4*)(X + (size_t)row0 * En);
    float4* xs4 = (float4*)xs;
#pragma unroll
    for (int i = 0; i < 4; i++) xs4[j + i * 256] = Xv[j + i * 256];
    __syncthreads();

#pragma unroll 2
    for (int r = 0; r < 64; r++) {
        const ulonglong2* xr = (const ulonglong2*)&xs[r * 64];
        u64 acc0 = pack2(bj, 0.f);
        u64 acc1 = pack2(0.f, 0.f);
#pragma unroll
        for (int kv = 0; kv < 16; kv++) {
            ulonglong2 v = xr[kv];
            acc0 = fma2(wp[2 * kv],     v.x, acc0);
            acc1 = fma2(wp[2 * kv + 1], v.y, acc1);
        }
        float a, b2, c, d;
        unpack2(acc0, a, b2);
        unpack2(acc1, c, d);
        XW[(size_t)(row0 + r) * Gn + j] = (a + b2) + (c + d);
    }
}

// ---------------------------------------------------------------------------
// LSTM recurrence. Grid = B/Rr = 128 blocks, 256 threads.
// Phase A: thread j computes z[r][j] = xw[b_r][t][j] + sum_k h[r][k]*Wh[k][j]
//          via packed f32x2 FMA (Wh column packed in 32 regs, h from smem).
// Phase B: thread j -> (r' = j>>6, hh = j&63) applies gates; c in register.
// ---------------------------------------------------------------------------
__global__ void __launch_bounds__(256)
lstm_kernel(const float* __restrict__ xw,   // [B*T, 256]
            const float* __restrict__ Wh,   // [64, 256]
            float* __restrict__ hout)       // [B*T, 64]
{
    const int j  = threadIdx.x;
    const int b0 = blockIdx.x * Rr;
    const int rp = j >> 6;        // phase-B row
    const int hh = j & 63;        // phase-B hidden index

    __shared__ __align__(16) float hs[Rr][Hn];
    __shared__ float zs[Rr][Gn];

    // Wh column j -> 32 packed pairs along k
    u64 wp[32];
#pragma unroll
    for (int m = 0; m < 32; m++)
        wp[m] = pack2(Wh[(2 * m) * Gn + j], Wh[(2 * m + 1) * Gn + j]);

    hs[rp][hh] = 0.f;
    float c = 0.f;

    // prefetch xw for t=0
    float xn[Rr];
#pragma unroll
    for (int r = 0; r < Rr; r++)
        xn[r] = xw[((size_t)(b0 + r) * Tn + 0) * Gn + j];

    __syncthreads();

    for (int t = 0; t < Tn; t++) {
        u64 acc0[Rr], acc1[Rr];
#pragma unroll
        for (int r = 0; r < Rr; r++) {
            acc0[r] = pack2(xn[r], 0.f);
            acc1[r] = pack2(0.f, 0.f);
        }

        // prefetch next step's xw (overlaps the dot phase)
        if (t + 1 < Tn) {
#pragma unroll
            for (int r = 0; r < Rr; r++)
                xn[r] = xw[((size_t)(b0 + r) * Tn + (t + 1)) * Gn + j];
        }

        // dot: z[r] += sum_k w[k] * h[r][k]  (packed pairs, 8 indep chains)
#pragma unroll
        for (int kv = 0; kv < 16; kv++) {
            const u64 w0 = wp[2 * kv];
            const u64 w1 = wp[2 * kv + 1];
#pragma unroll
            for (int r = 0; r < Rr; r++) {
                ulonglong2 hv = *(const ulonglong2*)&hs[r][4 * kv];
                acc0[r] = fma2(w0, hv.x, acc0[r]);
                acc1[r] = fma2(w1, hv.y, acc1[r]);
            }
        }
#pragma unroll
        for (int r = 0; r < Rr; r++) {
            float a, b2, cc, d;
            unpack2(acc0[r], a, b2);
            unpack2(acc1[r], cc, d);
            zs[r][j] = (a + b2) + (cc + d);
        }
        __syncthreads();

        // gates
        float zi = zs[rp][hh];
        float zf = zs[rp][64  + hh];
        float zg = zs[rp][128 + hh];
        float zo = zs[rp][192 + hh];

        float ig = sigf(zi);
        float fg = sigf(zf);
        float gg = tanhfast(zg);
        float og = sigf(zo);

        c = fg * c + ig * gg;
        float h = og * tanhfast(c);

        hs[rp][hh] = h;
        hout[((size_t)(b0 + rp) * Tn + t) * Hn + hh] = h;
        __syncthreads();
    }
}

// ---------------------------------------------------------------------------
// Logits + softmax, duplicated into both time halves (bwd == fwd).
// ---------------------------------------------------------------------------
__global__ void __launch_bounds__(256)
logits_kernel(const float* __restrict__ Hs,   // [B*T, 64]
              const float* __restrict__ Wd,   // [64, 8]
              const float* __restrict__ bd,   // [8]
              float* __restrict__ out)        // [B, 2T, 8]
{
    __shared__ float wd_s[Hn * Cn];
    __shared__ float bd_s[Cn];
    const int tid = threadIdx.x;
    for (int i = tid; i < Hn * Cn; i += 256) wd_s[i] = Wd[i];
    if (tid < Cn) bd_s[tid] = bd[tid];
    __syncthreads();

    const int row = blockIdx.x * 256 + tid;   // b*T + t
    float acc[Cn];
#pragma unroll
    for (int cc = 0; cc < Cn; cc++) acc[cc] = bd_s[cc];

    const float4* hr = (const float4*)(Hs + (size_t)row * Hn);
#pragma unroll
    for (int kv = 0; kv < 16; kv++) {
        float4 x = hr[kv];
#pragma unroll
        for (int cc = 0; cc < Cn; cc++) {
            acc[cc] += x.x * wd_s[(4*kv+0) * Cn + cc];
            acc[cc] += x.y * wd_s[(4*kv+1) * Cn + cc];
            acc[cc] += x.z * wd_s[(4*kv+2) * Cn + cc];
            acc[cc] += x.w * wd_s[(4*kv+3) * Cn + cc];
        }
    }

    float m = acc[0];
#pragma unroll
    for (int cc = 1; cc < Cn; cc++) m = fmaxf(m, acc[cc]);
    float s = 0.f;
    float e[Cn];
#pragma unroll
    for (int cc = 0; cc < Cn; cc++) { e[cc] = __expf(acc[cc] - m); s += e[cc]; }
    float inv = 1.f / s;

    const int b = row >> 9;          // row / T
    const int t = row & (Tn - 1);
    float4 r0, r1;
    r0.x = e[0]*inv; r0.y = e[1]*inv; r0.z = e[2]*inv; r0.w = e[3]*inv;
    r1.x = e[4]*inv; r1.y = e[5]*inv; r1.z = e[6]*inv; r1.w = e[7]*inv;

    float* o1 = out + ((size_t)b * (2 * Tn) + t) * Cn;
    float* o2 = o1 + (size_t)Tn * Cn;
    ((float4*)o1)[0] = r0; ((float4*)o1)[1] = r1;
    ((float4*)o2)[0] = r0; ((float4*)o2)[1] = r1;
}

// ---------------------------------------------------------------------------
// Launch
// ---------------------------------------------------------------------------
extern "C" void kernel_launch(void* const* d_in, const int* in_sizes, int n_in,
                              void* d_out, int out_size)
{
    const int*   ids        = (const int*)d_in[0];
    const float* word_table = (const float*)d_in[3];
    const float* pos_table  = (const float*)d_in[4];
    const float* Wx         = (const float*)d_in[5];
    const float* Wh         = (const float*)d_in[6];
    const float* b          = (const float*)d_in[7];
    const float* Wd         = (const float*)d_in[8];
    const float* bd         = (const float*)d_in[9];
    float* out = (float*)d_out;

    float *bufA, *bufB, *xwp;
    cudaGetSymbolAddress((void**)&bufA, g_bufA);
    cudaGetSymbolAddress((void**)&bufB, g_bufB);
    cudaGetSymbolAddress((void**)&xwp,  g_xw);

    // embedding
    embed_kernel<<<(Bn * Tn * 16) / 256, 256>>>(ids, word_table, pos_table, bufA);

    // layer 0
    gemm_xw_kernel<<<(Bn * Tn) / 64, 256>>>(bufA, Wx, b, xwp);
    lstm_kernel<<<Bn / Rr, 256>>>(xwp, Wh, bufB);

    // layer 1 (same weights, per reference loop)
    gemm_xw_kernel<<<(Bn * Tn) / 64, 256>>>(bufB, Wx, b, xwp);
    lstm_kernel<<<Bn / Rr, 256>>>(xwp, Wh, bufA);

    // classifier + softmax (writes both halves of the 2T axis)
    logits_kernel<<<(Bn * Tn) / 256, 256>>>(bufA, Wd, bd, out);
}

// round 4
// speedup vs baseline: 1.0695x; 1.0695x over previous
#include <cuda_runtime.h>
#include <cuda_bf16.h>
#include <cstdint>

// Problem constants
#define Bn 512
#define Tn 512
#define En 64
#define Hn 64
#define Gn 256   // 4*H
#define Cn 8
#define Rr 4     // batch rows per LSTM block
#define PF 4     // xw prefetch depth (steps)

typedef unsigned long long u64;

// Scratch (device globals: no cudaMalloc allowed)
__device__ float g_bufA[Bn * Tn * En];
__device__ float g_bufB[Bn * Tn * Hn];
__device__ float g_xw[Bn * Tn * Gn];

// ---------------------------------------------------------------------------
// packed f32x2 helpers
// ---------------------------------------------------------------------------
__device__ __forceinline__ u64 pack2(float lo, float hi) {
    u64 r; asm("mov.b64 %0, {%1, %2};" : "=l"(r) : "f"(lo), "f"(hi)); return r;
}
__device__ __forceinline__ void unpack2(u64 v, float& lo, float& hi) {
    asm("mov.b64 {%0, %1}, %2;" : "=f"(lo), "=f"(hi) : "l"(v));
}
__device__ __forceinline__ u64 fma2(u64 a, u64 b, u64 c) {
    u64 d; asm("fma.rn.f32x2 %0, %1, %2, %3;" : "=l"(d) : "l"(a), "l"(b), "l"(c));
    return d;
}

__device__ __forceinline__ float sigf(float x) {
    return 1.f / (1.f + __expf(-x));
}
__device__ __forceinline__ float tanhfast(float x) {
    return 2.f / (1.f + __expf(-2.f * x)) - 1.f;
}

// ---------------------------------------------------------------------------
// Embedding
// ---------------------------------------------------------------------------
__global__ void embed_kernel(const int* __restrict__ ids,
                             const float* __restrict__ wt,
                             const float* __restrict__ pt,
                             float* __restrict__ out)
{
    int i = blockIdx.x * blockDim.x + threadIdx.x;
    int bt = i >> 4;
    int v  = i & 15;
    int id = ids[bt];
    int t  = bt & (Tn - 1);
    float4 a = ((const float4*)wt)[id * 16 + v];
    float4 p = ((const float4*)pt)[t * 16 + v];
    float4 r;
    r.x = a.x + p.x; r.y = a.y + p.y; r.z = a.z + p.z; r.w = a.w + p.w;
    ((float4*)out)[i] = r;
}

// ---------------------------------------------------------------------------
// XW GEMM: XW[row][j] = sum_k X[row][k] * Wx[k][j] + b[j]
// 256 threads = 2 row-teams x 128 col-threads; each thread owns 2 columns
// (c, c+128) so one 16B broadcast LDS feeds 4 FFMA2 (LDS no longer binding).
// ---------------------------------------------------------------------------
__global__ void __launch_bounds__(256, 1)
gemm_xw_kernel(const float* __restrict__ X,
               const float* __restrict__ Wx,
               const float* __restrict__ bias,
               float* __restrict__ XW)
{
    const int tid  = threadIdx.x;
    const int team = tid >> 7;        // 0 / 1 : owns rows [team*32, team*32+32)
    const int tj   = tid & 127;
    const int c0   = tj;
    const int c1   = tj + 128;
    const int rowB = blockIdx.x * 64;

    __shared__ __align__(16) float xs[64 * 64];

    // weight columns c0, c1 packed along k
    u64 wp0[32], wp1[32];
#pragma unroll
    for (int m = 0; m < 32; m++) {
        wp0[m] = pack2(Wx[(2 * m) * Gn + c0], Wx[(2 * m + 1) * Gn + c0]);
        wp1[m] = pack2(Wx[(2 * m) * Gn + c1], Wx[(2 * m + 1) * Gn + c1]);
    }
    const float b0 = bias[c0];
    const float b1 = bias[c1];

    // cooperative load 64 rows x 64 cols
    const float4* Xv = (const float4*)(X + (size_t)rowB * En);
    float4* xs4 = (float4*)xs;
#pragma unroll
    for (int i = 0; i < 4; i++) xs4[tid + i * 256] = Xv[tid + i * 256];
    __syncthreads();

#pragma unroll 2
    for (int r = 0; r < 32; r++) {
        const int row = team * 32 + r;
        const ulonglong2* xr = (const ulonglong2*)&xs[row * 64];
        u64 a0 = pack2(b0, 0.f), a1 = 0ull;
        u64 d0 = pack2(b1, 0.f), d1 = 0ull;
#pragma unroll
        for (int kv = 0; kv < 16; kv++) {
            ulonglong2 v = xr[kv];
            a0 = fma2(wp0[2 * kv],     v.x, a0);
            a1 = fma2(wp0[2 * kv + 1], v.y, a1);
            d0 = fma2(wp1[2 * kv],     v.x, d0);
            d1 = fma2(wp1[2 * kv + 1], v.y, d1);
        }
        float p, q, s, t2;
        unpack2(a0, p, q); unpack2(a1, s, t2);
        XW[(size_t)(rowB + row) * Gn + c0] = (p + q) + (s + t2);
        unpack2(d0, p, q); unpack2(d1, s, t2);
        XW[(size_t)(rowB + row) * Gn + c1] = (p + q) + (s + t2);
    }
}

// ---------------------------------------------------------------------------
// LSTM recurrence with 4-step-deep xw register-ring prefetch.
// Grid = B/Rr = 128 blocks, 256 threads. Thread j = column j.
// ---------------------------------------------------------------------------
#define LSTM_STEP(T, RING)                                                    \
{                                                                             \
    u64 acc0[Rr], acc1[Rr];                                                   \
    _Pragma("unroll")                                                         \
    for (int r = 0; r < Rr; r++) {                                            \
        acc0[r] = pack2(RING[r], 0.f);                                        \
        acc1[r] = 0ull;                                                       \
    }                                                                         \
    /* refill this ring slot PF steps ahead (overlaps with dot phase) */      \
    {                                                                         \
        const int tl = (T) + PF;                                              \
        if (tl < Tn) {                                                        \
            _Pragma("unroll")                                                 \
            for (int r = 0; r < Rr; r++)                                      \
                RING[r] = xp[r][(size_t)tl * Gn];                             \
        }                                                                     \
    }                                                                         \
    _Pragma("unroll")                                                         \
    for (int kv = 0; kv < 16; kv++) {                                         \
        const u64 w0 = wp[2 * kv];                                            \
        const u64 w1 = wp[2 * kv + 1];                                        \
        _Pragma("unroll")                                                     \
        for (int r = 0; r < Rr; r++) {                                        \
            ulonglong2 hv = *(const ulonglong2*)&hs[r][4 * kv];               \
            acc0[r] = fma2(w0, hv.x, acc0[r]);                                \
            acc1[r] = fma2(w1, hv.y, acc1[r]);                                \
        }                                                                     \
    }                                                                         \
    _Pragma("unroll")                                                         \
    for (int r = 0; r < Rr; r++) {                                            \
        float a_, b_, c_, d_;                                                 \
        unpack2(acc0[r], a_, b_);                                             \
        unpack2(acc1[r], c_, d_);                                             \
        zs[r][j] = (a_ + b_) + (c_ + d_);                                     \
    }                                                                         \
    __syncthreads();                                                          \
    {                                                                         \
        float zi = zs[rp][hh];                                                \
        float zf = zs[rp][64  + hh];                                          \
        float zg = zs[rp][128 + hh];                                          \
        float zo = zs[rp][192 + hh];                                          \
        float ig = sigf(zi);                                                  \
        float fg = sigf(zf);                                                  \
        float gg = tanhfast(zg);                                              \
        float og = sigf(zo);                                                  \
        c = fg * c + ig * gg;                                                 \
        float h = og * tanhfast(c);                                           \
        hs[rp][hh] = h;                                                       \
        hrow[(size_t)(T) * Hn] = h;                                           \
    }                                                                         \
    __syncthreads();                                                          \
}

__global__ void __launch_bounds__(256, 1)
lstm_kernel(const float* __restrict__ xw,   // [B*T, 256]
            const float* __restrict__ Wh,   // [64, 256]
            float* __restrict__ hout)       // [B*T, 64]
{
    const int j  = threadIdx.x;
    const int b0 = blockIdx.x * Rr;
    const int rp = j >> 6;
    const int hh = j & 63;

    __shared__ __align__(16) float hs[Rr][Hn];
    __shared__ float zs[Rr][Gn];

    u64 wp[32];
#pragma unroll
    for (int m = 0; m < 32; m++)
        wp[m] = pack2(Wh[(2 * m) * Gn + j], Wh[(2 * m + 1) * Gn + j]);

    hs[rp][hh] = 0.f;
    float c = 0.f;

    const float* xp[Rr];
#pragma unroll
    for (int r = 0; r < Rr; r++)
        xp[r] = xw + (size_t)(b0 + r) * Tn * Gn + j;

    // prime the 4-slot ring with t = 0..3
    float ringA[Rr], ringB[Rr], ringC[Rr], ringD[Rr];
#pragma unroll
    for (int r = 0; r < Rr; r++) {
        ringA[r] = xp[r][(size_t)0 * Gn];
        ringB[r] = xp[r][(size_t)1 * Gn];
        ringC[r] = xp[r][(size_t)2 * Gn];
        ringD[r] = xp[r][(size_t)3 * Gn];
    }

    float* hrow = hout + (size_t)(b0 + rp) * Tn * Hn + hh;

    __syncthreads();

    for (int tb = 0; tb < Tn; tb += PF) {
        LSTM_STEP(tb + 0, ringA);
        LSTM_STEP(tb + 1, ringB);
        LSTM_STEP(tb + 2, ringC);
        LSTM_STEP(tb + 3, ringD);
    }
}

// ---------------------------------------------------------------------------
// Logits + softmax, duplicated into both time halves (bwd == fwd).
// ---------------------------------------------------------------------------
__global__ void __launch_bounds__(256)
logits_kernel(const float* __restrict__ Hs,
              const float* __restrict__ Wd,
              const float* __restrict__ bd,
              float* __restrict__ out)
{
    __shared__ float wd_s[Hn * Cn];
    __shared__ float bd_s[Cn];
    const int tid = threadIdx.x;
    for (int i = tid; i < Hn * Cn; i += 256) wd_s[i] = Wd[i];
    if (tid < Cn) bd_s[tid] = bd[tid];
    __syncthreads();

    const int row = blockIdx.x * 256 + tid;
    float acc[Cn];
#pragma unroll
    for (int cc = 0; cc < Cn; cc++) acc[cc] = bd_s[cc];

    const float4* hr = (const float4*)(Hs + (size_t)row * Hn);
#pragma unroll
    for (int kv = 0; kv < 16; kv++) {
        float4 x = hr[kv];
#pragma unroll
        for (int cc = 0; cc < Cn; cc++) {
            acc[cc] += x.x * wd_s[(4*kv+0) * Cn + cc];
            acc[cc] += x.y * wd_s[(4*kv+1) * Cn + cc];
            acc[cc] += x.z * wd_s[(4*kv+2) * Cn + cc];
            acc[cc] += x.w * wd_s[(4*kv+3) * Cn + cc];
        }
    }

    float m = acc[0];
#pragma unroll
    for (int cc = 1; cc < Cn; cc++) m = fmaxf(m, acc[cc]);
    float s = 0.f;
    float e[Cn];
#pragma unroll
    for (int cc = 0; cc < Cn; cc++) { e[cc] = __expf(acc[cc] - m); s += e[cc]; }
    float inv = 1.f / s;

    const int b = row >> 9;
    const int t = row & (Tn - 1);
    float4 r0, r1;
    r0.x = e[0]*inv; r0.y = e[1]*inv; r0.z = e[2]*inv; r0.w = e[3]*inv;
    r1.x = e[4]*inv; r1.y = e[5]*inv; r1.z = e[6]*inv; r1.w = e[7]*inv;

    float* o1 = out + ((size_t)b * (2 * Tn) + t) * Cn;
    float* o2 = o1 + (size_t)Tn * Cn;
    ((float4*)o1)[0] = r0; ((float4*)o1)[1] = r1;
    ((float4*)o2)[0] = r0; ((float4*)o2)[1] = r1;
}

// ---------------------------------------------------------------------------
// Launch
// ---------------------------------------------------------------------------
extern "C" void kernel_launch(void* const* d_in, const int* in_sizes, int n_in,
                              void* d_out, int out_size)
{
    const int*   ids        = (const int*)d_in[0];
    const float* word_table = (const float*)d_in[3];
    const float* pos_table  = (const float*)d_in[4];
    const float* Wx         = (const float*)d_in[5];
    const float* Wh         = (const float*)d_in[6];
    const float* b          = (const float*)d_in[7];
    const float* Wd         = (const float*)d_in[8];
    const float* bd         = (const float*)d_in[9];
    float* out = (float*)d_out;

    float *bufA, *bufB, *xwp;
    cudaGetSymbolAddress((void**)&bufA, g_bufA);
    cudaGetSymbolAddress((void**)&bufB, g_bufB);
    cudaGetSymbolAddress((void**)&xwp,  g_xw);

    embed_kernel<<<(Bn * Tn * 16) / 256, 256>>>(ids, word_table, pos_table, bufA);

    gemm_xw_kernel<<<(Bn * Tn) / 64, 256>>>(bufA, Wx, b, xwp);
    lstm_kernel<<<Bn / Rr, 256>>>(xwp, Wh, bufB);

    gemm_xw_kernel<<<(Bn * Tn) / 64, 256>>>(bufB, Wx, b, xwp);
    lstm_kernel<<<Bn / Rr, 256>>>(xwp, Wh, bufA);

    logits_kernel<<<(Bn * Tn) / 256, 256>>>(bufA, Wd, bd, out);
}